// round 14
// baseline (speedup 1.0000x reference)
#include <cuda_runtime.h>
#include <cuda_fp16.h>
#include <stdint.h>

#define USER_NUM 100000
#define ITEM_NUM 200000
#define NNODES   (USER_NUM + ITEM_NUM)   // 300000
#define EMB      64
#define TOT      (NNODES * EMB)
#define MAXE     2097152

#define SCAN_TPB 1024
#define NSCANBLK ((NNODES + SCAN_TPB - 1) / SCAN_TPB)   // 293

// ---- static scratch (no cudaMalloc allowed) ----
// INVARIANT: g_counts == 0 at entry of every kernel_launch call.
__device__ int   g_counts[NNODES];
__device__ int   g_cursor[NNODES];         // zeroed by scan1, used by fill
__device__ int2  g_off2[NNODES];           // {row start, row end} (paired offsets)
__device__ int   g_blocksums[NSCANBLK];
__device__ int2  g_csr_cv[MAXE];           // packed (col, val-as-bits)
__device__ uint4 g_bufA[TOT / 8];          // fp16 e2  (row = 8 uint4 = 64 halfs)
__device__ uint4 g_bufB[TOT / 8];          // fp16 e1

// ---------------------------------------------------------------------------
// hist: 4 edges per thread (one int4 load), fire-and-forget REDs
__global__ void hist_kernel(const int4* __restrict__ rows4, int* __restrict__ counts,
                            int n4) {
    int i = blockIdx.x * blockDim.x + threadIdx.x;
    if (i >= n4) return;
    int4 r = __ldg(rows4 + i);
    atomicAdd(&counts[r.x], 1);
    atomicAdd(&counts[r.y], 1);
    atomicAdd(&counts[r.z], 1);
    atomicAdd(&counts[r.w], 1);
}
__global__ void hist_tail_kernel(const int* __restrict__ rows, int* __restrict__ counts,
                                 int start, int n) {
    int i = start + blockIdx.x * blockDim.x + threadIdx.x;
    if (i < n) atomicAdd(&counts[rows[i]], 1);
}

// block-local scan (warp shuffles, 2 barriers); emits {start,end} pairs;
// zeroes counts + cursor
__global__ void scan1_kernel(int* __restrict__ counts, int* __restrict__ cursor,
                             int2* __restrict__ off2, int* __restrict__ blocksums) {
    __shared__ int wsum[SCAN_TPB / 32];
    int tid  = threadIdx.x;
    int lane = tid & 31;
    int wid  = tid >> 5;
    int gid  = blockIdx.x * SCAN_TPB + tid;

    int v = (gid < NNODES) ? counts[gid] : 0;
    int incl = v;
#pragma unroll
    for (int o = 1; o < 32; o <<= 1) {
        int t = __shfl_up_sync(0xFFFFFFFF, incl, o);
        if (lane >= o) incl += t;
    }
    if (lane == 31) wsum[wid] = incl;
    __syncthreads();
    if (wid == 0) {
        int w = wsum[lane];
#pragma unroll
        for (int o = 1; o < 32; o <<= 1) {
            int t = __shfl_up_sync(0xFFFFFFFF, w, o);
            if (lane >= o) w += t;
        }
        wsum[lane] = w;
    }
    __syncthreads();
    int add = (wid > 0) ? wsum[wid - 1] : 0;
    incl += add;

    if (gid < NNODES) {
        off2[gid]   = make_int2(incl - v, incl);   // {start, end} (block-local)
        counts[gid] = 0;
        cursor[gid] = 0;
    }
    if (tid == SCAN_TPB - 1) blocksums[blockIdx.x] = incl;
}

// fused scan2+scan3: per-block prefix of blocksums, added to both pair fields
__global__ void scan23_kernel(int2* __restrict__ off2, const int* __restrict__ blocksums) {
    __shared__ int red[SCAN_TPB / 32];
    int tid = threadIdx.x;
    int blk = blockIdx.x;

    int part = (tid < blk) ? blocksums[tid] : 0;     // blk <= 292 < 1024
#pragma unroll
    for (int o = 16; o > 0; o >>= 1)
        part += __shfl_down_sync(0xFFFFFFFF, part, o);
    if ((tid & 31) == 0) red[tid >> 5] = part;
    __syncthreads();
    if (tid < 32) {
        int w = (tid < SCAN_TPB / 32) ? red[tid] : 0;
#pragma unroll
        for (int o = 16; o > 0; o >>= 1)
            w += __shfl_down_sync(0xFFFFFFFF, w, o);
        if (tid == 0) red[0] = w;
    }
    __syncthreads();
    int base = red[0];

    int gid = blk * SCAN_TPB + tid;
    if (gid < NNODES) {
        int2 p = off2[gid];
        off2[gid] = make_int2(p.x + base, p.y + base);
    }
}

__global__ void fill_kernel(const int* __restrict__ rows, const int* __restrict__ cols,
                            const float* __restrict__ vals,
                            const int2* __restrict__ off2, int* __restrict__ cursor,
                            int2* __restrict__ csr_cv, int n) {
    int e = blockIdx.x * blockDim.x + threadIdx.x;
    if (e >= n) return;
    int r = rows[e];
    int pos = __ldg(off2 + r).x + atomicAdd(&cursor[r], 1);
    csr_cv[pos] = make_int2(cols[e], __float_as_int(vals[e]));
}

// ---------------------------------------------------------------------------
__device__ __forceinline__ uint4 pack8(const float f[8]) {
    __half2 h0 = __float22half2_rn(make_float2(f[0], f[1]));
    __half2 h1 = __float22half2_rn(make_float2(f[2], f[3]));
    __half2 h2 = __float22half2_rn(make_float2(f[4], f[5]));
    __half2 h3 = __float22half2_rn(make_float2(f[6], f[7]));
    uint4 o;
    o.x = *reinterpret_cast<unsigned*>(&h0);
    o.y = *reinterpret_cast<unsigned*>(&h1);
    o.z = *reinterpret_cast<unsigned*>(&h2);
    o.w = *reinterpret_cast<unsigned*>(&h3);
    return o;
}
__device__ __forceinline__ void hacc4(__half2 acc[4], uint4 raw, float v) {
    __half2 vh = __half2half2(__float2half_rn(v));
    __half2* h = reinterpret_cast<__half2*>(&raw);
#pragma unroll
    for (int j = 0; j < 4; ++j) acc[j] = __hfma2(vh, h[j], acc[j]);
}
__device__ __forceinline__ void facc8(float a[8], const float4& x0, const float4& x1, float v) {
    a[0] += v*x0.x; a[1] += v*x0.y; a[2] += v*x0.z; a[3] += v*x0.w;
    a[4] += v*x1.x; a[5] += v*x1.y; a[6] += v*x1.z; a[7] += v*x1.w;
}
__device__ __forceinline__ const float4* egoptr(int c, const float4* user,
                                                const float4* item, int l) {
    return (c < USER_NUM) ? (user + (size_t)c * 16 + l * 2)
                          : (item + (size_t)(c - USER_NUM) * 16 + l * 2);
}

// ---------------------------------------------------------------------------
// CSR SpMM, 8 lanes/row, predicated 4-edge batches (clamped idx, zeroed OOB
// weight). Row bounds come from ONE paired-offset LDG.64.
//   MODE 0: fp32 ego gather, fp32 acc -> fp16 store
//   MODE 1: fp16 gather, HFMA2 acc   -> fp16 store
//   MODE 2: like 1, epilogue out = (ego + B + A + s) * 0.25 (fp32)
// ---------------------------------------------------------------------------
template <int MODE>
__global__ __launch_bounds__(256) void spmm_csr_kernel(
        const int2* __restrict__ off2,
        const int2* __restrict__ cv,
        const uint4* __restrict__ xh,
        const float4* __restrict__ user,
        const float4* __restrict__ item,
        uint4* __restrict__ nexth,
        const uint4* __restrict__ bh,
        const uint4* __restrict__ ah,
        float4* __restrict__ out) {
    int t = blockIdx.x * blockDim.x + threadIdx.x;
    int r = t >> 3;
    int l = t & 7;
    if (r >= NNODES) return;

    int2 se = __ldg(off2 + r);
    int s = se.x, e = se.y;

    if (MODE == 0) {
        float a[8];
#pragma unroll
        for (int j = 0; j < 8; ++j) a[j] = 0.f;
        for (int base = s; base < e; base += 4) {
            int last = e - 1;
            int i1 = base + 1 <= last ? base + 1 : last;
            int i2 = base + 2 <= last ? base + 2 : last;
            int i3 = base + 3 <= last ? base + 3 : last;
            int2 c0 = __ldg(cv + base);
            int2 c1 = __ldg(cv + i1);
            int2 c2 = __ldg(cv + i2);
            int2 c3 = __ldg(cv + i3);
            const float4* p0 = egoptr(c0.x, user, item, l);
            const float4* p1 = egoptr(c1.x, user, item, l);
            const float4* p2 = egoptr(c2.x, user, item, l);
            const float4* p3 = egoptr(c3.x, user, item, l);
            float4 x00 = __ldg(p0), x01 = __ldg(p0 + 1);
            float4 x10 = __ldg(p1), x11 = __ldg(p1 + 1);
            float4 x20 = __ldg(p2), x21 = __ldg(p2 + 1);
            float4 x30 = __ldg(p3), x31 = __ldg(p3 + 1);
            float v0 = __int_as_float(c0.y);
            float v1 = (base + 1 < e) ? __int_as_float(c1.y) : 0.f;
            float v2 = (base + 2 < e) ? __int_as_float(c2.y) : 0.f;
            float v3 = (base + 3 < e) ? __int_as_float(c3.y) : 0.f;
            facc8(a, x00, x01, v0);
            facc8(a, x10, x11, v1);
            facc8(a, x20, x21, v2);
            facc8(a, x30, x31, v3);
        }
        nexth[(size_t)r * 8 + l] = pack8(a);
        return;
    }

    // MODE 1 / 2: batch 4
    __half2 acc[4];
    __half2 z = __half2half2(__float2half_rn(0.f));
#pragma unroll
    for (int j = 0; j < 4; ++j) acc[j] = z;

    for (int base = s; base < e; base += 4) {
        int last = e - 1;
        int i1 = base + 1 <= last ? base + 1 : last;
        int i2 = base + 2 <= last ? base + 2 : last;
        int i3 = base + 3 <= last ? base + 3 : last;
        int2 c0 = __ldg(cv + base);
        int2 c1 = __ldg(cv + i1);
        int2 c2 = __ldg(cv + i2);
        int2 c3 = __ldg(cv + i3);
        uint4 x0 = __ldg(xh + (size_t)c0.x * 8 + l);
        uint4 x1 = __ldg(xh + (size_t)c1.x * 8 + l);
        uint4 x2 = __ldg(xh + (size_t)c2.x * 8 + l);
        uint4 x3 = __ldg(xh + (size_t)c3.x * 8 + l);
        float v0 = __int_as_float(c0.y);
        float v1 = (base + 1 < e) ? __int_as_float(c1.y) : 0.f;
        float v2 = (base + 2 < e) ? __int_as_float(c2.y) : 0.f;
        float v3 = (base + 3 < e) ? __int_as_float(c3.y) : 0.f;
        hacc4(acc, x0, v0);
        hacc4(acc, x1, v1);
        hacc4(acc, x2, v2);
        hacc4(acc, x3, v3);
    }

    if (MODE == 1) {
        uint4 o;
        o.x = *reinterpret_cast<unsigned*>(&acc[0]);
        o.y = *reinterpret_cast<unsigned*>(&acc[1]);
        o.z = *reinterpret_cast<unsigned*>(&acc[2]);
        o.w = *reinterpret_cast<unsigned*>(&acc[3]);
        nexth[(size_t)r * 8 + l] = o;
    } else {
        size_t fo = (size_t)r * 16 + l * 2;
        const float4* egop = (r < USER_NUM)
            ? (user + fo)
            : (item + (size_t)(r - USER_NUM) * 16 + l * 2);
        float4 e0 = __ldg(egop);
        float4 e1 = __ldg(egop + 1);
        uint4 braw = __ldg(bh + (size_t)r * 8 + l);
        uint4 araw = __ldg(ah + (size_t)r * 8 + l);
        __half2* bhh = reinterpret_cast<__half2*>(&braw);
        __half2* ahh = reinterpret_cast<__half2*>(&araw);
        float2 b0 = __half22float2(bhh[0]), b1 = __half22float2(bhh[1]);
        float2 b2 = __half22float2(bhh[2]), b3 = __half22float2(bhh[3]);
        float2 q0 = __half22float2(ahh[0]), q1 = __half22float2(ahh[1]);
        float2 q2 = __half22float2(ahh[2]), q3 = __half22float2(ahh[3]);
        float2 s0 = __half22float2(acc[0]), s1 = __half22float2(acc[1]);
        float2 s2 = __half22float2(acc[2]), s3 = __half22float2(acc[3]);
        float4 o0, o1;
        o0.x = (e0.x + b0.x + q0.x + s0.x) * 0.25f;
        o0.y = (e0.y + b0.y + q0.y + s0.y) * 0.25f;
        o0.z = (e0.z + b1.x + q1.x + s1.x) * 0.25f;
        o0.w = (e0.w + b1.y + q1.y + s1.y) * 0.25f;
        o1.x = (e1.x + b2.x + q2.x + s2.x) * 0.25f;
        o1.y = (e1.y + b2.y + q2.y + s2.y) * 0.25f;
        o1.z = (e1.z + b3.x + q3.x + s3.x) * 0.25f;
        o1.w = (e1.w + b3.y + q3.y + s3.y) * 0.25f;
        out[fo]     = o0;
        out[fo + 1] = o1;
    }
}

// ---------------------------------------------------------------------------
extern "C" void kernel_launch(void* const* d_in, const int* in_sizes, int n_in,
                              void* d_out, int out_size) {
    const float* user = (const float*)d_in[0];
    const float* item = (const float*)d_in[1];
    const float* vals = (const float*)d_in[2];
    const int*   rows = (const int*)  d_in[3];
    const int*   cols = (const int*)  d_in[4];
    const int n_edges = in_sizes[2];

    float4* out = (float4*)d_out;

    int *counts, *cursor, *blocksums;
    int2 *off2, *csr_cv;
    uint4 *A, *B;
    cudaGetSymbolAddress((void**)&counts,    g_counts);
    cudaGetSymbolAddress((void**)&cursor,    g_cursor);
    cudaGetSymbolAddress((void**)&off2,      g_off2);
    cudaGetSymbolAddress((void**)&blocksums, g_blocksums);
    cudaGetSymbolAddress((void**)&csr_cv,    g_csr_cv);
    cudaGetSymbolAddress((void**)&A,         g_bufA);
    cudaGetSymbolAddress((void**)&B,         g_bufB);

    const int TPB = 256;
    const int n4 = n_edges >> 2;                      // int4-vectorized edges
    const int tail_start = n4 << 2;
    const int grid_hist  = (n4 + TPB - 1) / TPB;
    const int grid_edges = (n_edges + TPB - 1) / TPB;
    const int grid_spmm  = (NNODES * 8 + TPB - 1) / TPB;

    // ---- CSR build (counts==0 invariant at entry) ----
    if (n4 > 0)
        hist_kernel<<<grid_hist, TPB>>>((const int4*)rows, counts, n4);
    if (tail_start < n_edges)
        hist_tail_kernel<<<1, TPB>>>(rows, counts, tail_start, n_edges);
    scan1_kernel<<<NSCANBLK, SCAN_TPB>>>(counts, cursor, off2, blocksums);
    scan23_kernel<<<NSCANBLK, SCAN_TPB>>>(off2, blocksums);
    fill_kernel<<<grid_edges, TPB>>>(rows, cols, vals, off2, cursor,
                                     csr_cv, n_edges);

    // ---- 3 propagation layers ----
    spmm_csr_kernel<0><<<grid_spmm, TPB>>>(off2, csr_cv, nullptr,
                                           (const float4*)user, (const float4*)item,
                                           B, nullptr, nullptr, nullptr);
    spmm_csr_kernel<1><<<grid_spmm, TPB>>>(off2, csr_cv, B,
                                           (const float4*)user, (const float4*)item,
                                           A, nullptr, nullptr, nullptr);
    spmm_csr_kernel<2><<<grid_spmm, TPB>>>(off2, csr_cv, A,
                                           (const float4*)user, (const float4*)item,
                                           nullptr, B, A, out);
}

// round 15
// speedup vs baseline: 1.0707x; 1.0707x over previous
#include <cuda_runtime.h>
#include <cuda_fp16.h>
#include <stdint.h>

#define USER_NUM 100000
#define ITEM_NUM 200000
#define NNODES   (USER_NUM + ITEM_NUM)   // 300000
#define EMB      64
#define TOT      (NNODES * EMB)
#define MAXE     2097152

#define SCAN_TPB 1024
#define NSCANBLK ((NNODES + SCAN_TPB - 1) / SCAN_TPB)   // 293

// ---- static scratch (no cudaMalloc allowed) ----
// INVARIANT: g_counts == 0 at entry of every kernel_launch call.
// (BSS-zeroed at load; hist fills it, scan1 re-zeroes it, nothing else writes.)
__device__ int   g_counts[NNODES];
__device__ int   g_cursor[NNODES];         // zeroed by scan1 each call, used by fill
__device__ int   g_offsets[NNODES + 1];
__device__ int   g_blocksums[NSCANBLK];
__device__ int2  g_csr_cv[MAXE];           // packed (col, val-as-bits)
__device__ uint4 g_bufA[TOT / 8];          // fp16 e2  (row = 8 uint4 = 64 halfs)
__device__ uint4 g_bufB[TOT / 8];          // fp16 e1

// ---------------------------------------------------------------------------
// hist: 4 edges per thread (one int4 load), fire-and-forget REDs (no return)
__global__ void hist4_kernel(const int4* __restrict__ rows4, int* __restrict__ counts,
                             int n4) {
    int i = blockIdx.x * blockDim.x + threadIdx.x;
    if (i >= n4) return;
    int4 r = __ldg(rows4 + i);
    atomicAdd(&counts[r.x], 1);
    atomicAdd(&counts[r.y], 1);
    atomicAdd(&counts[r.z], 1);
    atomicAdd(&counts[r.w], 1);
}
__global__ void hist_tail_kernel(const int* __restrict__ rows, int* __restrict__ counts,
                                 int start, int n) {
    int i = start + blockIdx.x * blockDim.x + threadIdx.x;
    if (i < n) atomicAdd(&counts[rows[i]], 1);
}

// block-local exclusive scan; emits block totals; zeroes counts + cursor
__global__ void scan1_kernel(int* __restrict__ counts, int* __restrict__ cursor,
                             int* __restrict__ offsets, int* __restrict__ blocksums) {
    __shared__ int sh[SCAN_TPB];
    int tid = threadIdx.x;
    int gid = blockIdx.x * SCAN_TPB + tid;
    int v = (gid < NNODES) ? counts[gid] : 0;
    sh[tid] = v;
    __syncthreads();
    for (int off = 1; off < SCAN_TPB; off <<= 1) {
        int t = (tid >= off) ? sh[tid - off] : 0;
        __syncthreads();
        sh[tid] += t;
        __syncthreads();
    }
    if (gid < NNODES) {
        offsets[gid] = sh[tid] - v;   // exclusive within block
        counts[gid]  = 0;             // restore invariant
        cursor[gid]  = 0;             // reset fill cursor
    }
    if (tid == SCAN_TPB - 1) blocksums[blockIdx.x] = sh[tid];
}

// fused scan2+scan3: each block reduces blocksums[0..blk) itself, adds to offsets
__global__ void scan23_kernel(int* __restrict__ offsets, const int* __restrict__ blocksums,
                              int n_edges) {
    __shared__ int red[SCAN_TPB / 32];
    int tid = threadIdx.x;
    int blk = blockIdx.x;

    int part = (tid < blk) ? blocksums[tid] : 0;     // blk <= 292 < 1024
#pragma unroll
    for (int o = 16; o > 0; o >>= 1)
        part += __shfl_down_sync(0xFFFFFFFF, part, o);
    if ((tid & 31) == 0) red[tid >> 5] = part;
    __syncthreads();
    if (tid < 32) {
        int w = (tid < SCAN_TPB / 32) ? red[tid] : 0;
#pragma unroll
        for (int o = 16; o > 0; o >>= 1)
            w += __shfl_down_sync(0xFFFFFFFF, w, o);
        if (tid == 0) red[0] = w;
    }
    __syncthreads();
    int base = red[0];

    int gid = blk * SCAN_TPB + tid;
    if (gid < NNODES) offsets[gid] += base;
    if (gid == 0) offsets[NNODES] = n_edges;
}

__global__ void fill_kernel(const int* __restrict__ rows, const int* __restrict__ cols,
                            const float* __restrict__ vals,
                            const int* __restrict__ offsets, int* __restrict__ cursor,
                            int2* __restrict__ csr_cv, int n) {
    int e = blockIdx.x * blockDim.x + threadIdx.x;
    if (e >= n) return;
    int r = rows[e];
    int pos = offsets[r] + atomicAdd(&cursor[r], 1);
    csr_cv[pos] = make_int2(cols[e], __float_as_int(vals[e]));
}

// ---------------------------------------------------------------------------
__device__ __forceinline__ uint4 pack8(const float f[8]) {
    __half2 h0 = __float22half2_rn(make_float2(f[0], f[1]));
    __half2 h1 = __float22half2_rn(make_float2(f[2], f[3]));
    __half2 h2 = __float22half2_rn(make_float2(f[4], f[5]));
    __half2 h3 = __float22half2_rn(make_float2(f[6], f[7]));
    uint4 o;
    o.x = *reinterpret_cast<unsigned*>(&h0);
    o.y = *reinterpret_cast<unsigned*>(&h1);
    o.z = *reinterpret_cast<unsigned*>(&h2);
    o.w = *reinterpret_cast<unsigned*>(&h3);
    return o;
}
__device__ __forceinline__ void hacc4(__half2 acc[4], uint4 raw, float v) {
    __half2 vh = __half2half2(__float2half_rn(v));
    __half2* h = reinterpret_cast<__half2*>(&raw);
#pragma unroll
    for (int j = 0; j < 4; ++j) acc[j] = __hfma2(vh, h[j], acc[j]);
}
__device__ __forceinline__ void facc8(float a[8], const float4& x0, const float4& x1, float v) {
    a[0] += v*x0.x; a[1] += v*x0.y; a[2] += v*x0.z; a[3] += v*x0.w;
    a[4] += v*x1.x; a[5] += v*x1.y; a[6] += v*x1.z; a[7] += v*x1.w;
}
__device__ __forceinline__ const float4* egoptr(int c, const float4* user,
                                                const float4* item, int l) {
    return (c < USER_NUM) ? (user + (size_t)c * 16 + l * 2)
                          : (item + (size_t)(c - USER_NUM) * 16 + l * 2);
}

// ---------------------------------------------------------------------------
// CSR SpMM, 8 lanes/row, predicated 4-edge batches (clamped idx, zeroed OOB
// weight) — every row takes the parallel path. [R10 proven configuration]
//   MODE 0: fp32 ego gather, fp32 acc -> fp16 store
//   MODE 1: fp16 gather, HFMA2 acc   -> fp16 store
//   MODE 2: like 1, epilogue out = (ego + B + A + s) * 0.25 (fp32, streaming)
// ---------------------------------------------------------------------------
template <int MODE>
__global__ __launch_bounds__(256) void spmm_csr_kernel(
        const int*  __restrict__ offsets,
        const int2* __restrict__ cv,
        const uint4* __restrict__ xh,
        const float4* __restrict__ user,
        const float4* __restrict__ item,
        uint4* __restrict__ nexth,
        const uint4* __restrict__ bh,
        const uint4* __restrict__ ah,
        float4* __restrict__ out) {
    int t = blockIdx.x * blockDim.x + threadIdx.x;
    int r = t >> 3;
    int l = t & 7;
    if (r >= NNODES) return;

    int s = __ldg(offsets + r);
    int e = __ldg(offsets + r + 1);

    if (MODE == 0) {
        float a[8];
#pragma unroll
        for (int j = 0; j < 8; ++j) a[j] = 0.f;
        for (int base = s; base < e; base += 4) {
            int last = e - 1;
            int i1 = base + 1 <= last ? base + 1 : last;
            int i2 = base + 2 <= last ? base + 2 : last;
            int i3 = base + 3 <= last ? base + 3 : last;
            int2 c0 = __ldg(cv + base);
            int2 c1 = __ldg(cv + i1);
            int2 c2 = __ldg(cv + i2);
            int2 c3 = __ldg(cv + i3);
            const float4* p0 = egoptr(c0.x, user, item, l);
            const float4* p1 = egoptr(c1.x, user, item, l);
            const float4* p2 = egoptr(c2.x, user, item, l);
            const float4* p3 = egoptr(c3.x, user, item, l);
            float4 x00 = __ldg(p0), x01 = __ldg(p0 + 1);
            float4 x10 = __ldg(p1), x11 = __ldg(p1 + 1);
            float4 x20 = __ldg(p2), x21 = __ldg(p2 + 1);
            float4 x30 = __ldg(p3), x31 = __ldg(p3 + 1);
            float v0 = __int_as_float(c0.y);
            float v1 = (base + 1 < e) ? __int_as_float(c1.y) : 0.f;
            float v2 = (base + 2 < e) ? __int_as_float(c2.y) : 0.f;
            float v3 = (base + 3 < e) ? __int_as_float(c3.y) : 0.f;
            facc8(a, x00, x01, v0);
            facc8(a, x10, x11, v1);
            facc8(a, x20, x21, v2);
            facc8(a, x30, x31, v3);
        }
        nexth[(size_t)r * 8 + l] = pack8(a);
        return;
    }

    // MODE 1 / 2: batch 4
    __half2 acc[4];
    __half2 z = __half2half2(__float2half_rn(0.f));
#pragma unroll
    for (int j = 0; j < 4; ++j) acc[j] = z;

    for (int base = s; base < e; base += 4) {
        int last = e - 1;
        int i1 = base + 1 <= last ? base + 1 : last;
        int i2 = base + 2 <= last ? base + 2 : last;
        int i3 = base + 3 <= last ? base + 3 : last;
        int2 c0 = __ldg(cv + base);
        int2 c1 = __ldg(cv + i1);
        int2 c2 = __ldg(cv + i2);
        int2 c3 = __ldg(cv + i3);
        uint4 x0 = __ldg(xh + (size_t)c0.x * 8 + l);
        uint4 x1 = __ldg(xh + (size_t)c1.x * 8 + l);
        uint4 x2 = __ldg(xh + (size_t)c2.x * 8 + l);
        uint4 x3 = __ldg(xh + (size_t)c3.x * 8 + l);
        float v0 = __int_as_float(c0.y);
        float v1 = (base + 1 < e) ? __int_as_float(c1.y) : 0.f;
        float v2 = (base + 2 < e) ? __int_as_float(c2.y) : 0.f;
        float v3 = (base + 3 < e) ? __int_as_float(c3.y) : 0.f;
        hacc4(acc, x0, v0);
        hacc4(acc, x1, v1);
        hacc4(acc, x2, v2);
        hacc4(acc, x3, v3);
    }

    if (MODE == 1) {
        uint4 o;
        o.x = *reinterpret_cast<unsigned*>(&acc[0]);
        o.y = *reinterpret_cast<unsigned*>(&acc[1]);
        o.z = *reinterpret_cast<unsigned*>(&acc[2]);
        o.w = *reinterpret_cast<unsigned*>(&acc[3]);
        nexth[(size_t)r * 8 + l] = o;
    } else {
        size_t fo = (size_t)r * 16 + l * 2;
        const float4* egop = (r < USER_NUM)
            ? (user + fo)
            : (item + (size_t)(r - USER_NUM) * 16 + l * 2);
        float4 e0 = __ldg(egop);
        float4 e1 = __ldg(egop + 1);
        uint4 braw = __ldg(bh + (size_t)r * 8 + l);
        uint4 araw = __ldg(ah + (size_t)r * 8 + l);
        __half2* bhh = reinterpret_cast<__half2*>(&braw);
        __half2* ahh = reinterpret_cast<__half2*>(&araw);
        float2 b0 = __half22float2(bhh[0]), b1 = __half22float2(bhh[1]);
        float2 b2 = __half22float2(bhh[2]), b3 = __half22float2(bhh[3]);
        float2 q0 = __half22float2(ahh[0]), q1 = __half22float2(ahh[1]);
        float2 q2 = __half22float2(ahh[2]), q3 = __half22float2(ahh[3]);
        float2 s0 = __half22float2(acc[0]), s1 = __half22float2(acc[1]);
        float2 s2 = __half22float2(acc[2]), s3 = __half22float2(acc[3]);
        float4 o0, o1;
        o0.x = (e0.x + b0.x + q0.x + s0.x) * 0.25f;
        o0.y = (e0.y + b0.y + q0.y + s0.y) * 0.25f;
        o0.z = (e0.z + b1.x + q1.x + s1.x) * 0.25f;
        o0.w = (e0.w + b1.y + q1.y + s1.y) * 0.25f;
        o1.x = (e1.x + b2.x + q2.x + s2.x) * 0.25f;
        o1.y = (e1.y + b2.y + q2.y + s2.y) * 0.25f;
        o1.z = (e1.z + b3.x + q3.x + s3.x) * 0.25f;
        o1.w = (e1.w + b3.y + q3.y + s3.y) * 0.25f;
        // streaming stores: out is never re-read; don't evict gather table
        __stcs(&out[fo],     o0);
        __stcs(&out[fo + 1], o1);
    }
}

// ---------------------------------------------------------------------------
extern "C" void kernel_launch(void* const* d_in, const int* in_sizes, int n_in,
                              void* d_out, int out_size) {
    const float* user = (const float*)d_in[0];
    const float* item = (const float*)d_in[1];
    const float* vals = (const float*)d_in[2];
    const int*   rows = (const int*)  d_in[3];
    const int*   cols = (const int*)  d_in[4];
    const int n_edges = in_sizes[2];

    float4* out = (float4*)d_out;

    int *counts, *cursor, *offsets, *blocksums;
    int2 *csr_cv;
    uint4 *A, *B;
    cudaGetSymbolAddress((void**)&counts,    g_counts);
    cudaGetSymbolAddress((void**)&cursor,    g_cursor);
    cudaGetSymbolAddress((void**)&offsets,   g_offsets);
    cudaGetSymbolAddress((void**)&blocksums, g_blocksums);
    cudaGetSymbolAddress((void**)&csr_cv,    g_csr_cv);
    cudaGetSymbolAddress((void**)&A,         g_bufA);
    cudaGetSymbolAddress((void**)&B,         g_bufB);

    const int TPB = 256;
    const int n4 = n_edges >> 2;
    const int tail_start = n4 << 2;
    const int grid_hist  = (n4 + TPB - 1) / TPB;
    const int grid_edges = (n_edges + TPB - 1) / TPB;
    const int grid_spmm  = (NNODES * 8 + TPB - 1) / TPB;

    // ---- CSR build (counts==0 invariant at entry) ----
    if (n4 > 0)
        hist4_kernel<<<grid_hist, TPB>>>((const int4*)rows, counts, n4);
    if (tail_start < n_edges)
        hist_tail_kernel<<<1, TPB>>>(rows, counts, tail_start, n_edges);
    scan1_kernel<<<NSCANBLK, SCAN_TPB>>>(counts, cursor, offsets, blocksums);
    scan23_kernel<<<NSCANBLK, SCAN_TPB>>>(offsets, blocksums, n_edges);
    fill_kernel<<<grid_edges, TPB>>>(rows, cols, vals, offsets, cursor,
                                     csr_cv, n_edges);

    // ---- 3 propagation layers ----
    spmm_csr_kernel<0><<<grid_spmm, TPB>>>(offsets, csr_cv, nullptr,
                                           (const float4*)user, (const float4*)item,
                                           B, nullptr, nullptr, nullptr);
    spmm_csr_kernel<1><<<grid_spmm, TPB>>>(offsets, csr_cv, B,
                                           (const float4*)user, (const float4*)item,
                                           A, nullptr, nullptr, nullptr);
    spmm_csr_kernel<2><<<grid_spmm, TPB>>>(offsets, csr_cv, A,
                                           (const float4*)user, (const float4*)item,
                                           nullptr, B, A, out);
}

// round 16
// speedup vs baseline: 1.0864x; 1.0147x over previous
#include <cuda_runtime.h>
#include <cuda_fp16.h>
#include <stdint.h>

#define USER_NUM 100000
#define ITEM_NUM 200000
#define NNODES   (USER_NUM + ITEM_NUM)   // 300000
#define EMB      64
#define TOT      (NNODES * EMB)
#define MAXE     2097152

#define SCAN_TPB 1024
#define NSCANBLK ((NNODES + SCAN_TPB - 1) / SCAN_TPB)   // 293

// ---- static scratch (no cudaMalloc allowed) ----
// INVARIANT: g_counts == 0 at entry of every kernel_launch call.
// (BSS-zeroed at load; hist fills it, scan1 re-zeroes it, nothing else writes.)
__device__ int   g_counts[NNODES];
__device__ int   g_cursor[NNODES];         // zeroed by scan1 each call, used by fill
__device__ int   g_offsets[NNODES + 1];
__device__ int   g_blocksums[NSCANBLK];
__device__ int2  g_csr_cv[MAXE];           // packed (col, val-as-bits)
__device__ uint4 g_bufA[TOT / 8];          // fp16 e2  (row = 8 uint4 = 64 halfs)
__device__ uint4 g_bufB[TOT / 8];          // fp16 e1

// ---------------------------------------------------------------------------
__global__ void hist_kernel(const int* __restrict__ rows, int* __restrict__ counts, int n) {
    int i = blockIdx.x * blockDim.x + threadIdx.x;
    if (i < n) atomicAdd(&counts[rows[i]], 1);
}

// block-local exclusive scan via warp shuffles (2 barriers, not 20);
// emits block totals; zeroes counts + cursor
__global__ void scan1_kernel(int* __restrict__ counts, int* __restrict__ cursor,
                             int* __restrict__ offsets, int* __restrict__ blocksums) {
    __shared__ int wsum[SCAN_TPB / 32];
    int tid  = threadIdx.x;
    int lane = tid & 31;
    int wid  = tid >> 5;
    int gid  = blockIdx.x * SCAN_TPB + tid;

    int v = (gid < NNODES) ? counts[gid] : 0;
    int incl = v;
#pragma unroll
    for (int o = 1; o < 32; o <<= 1) {
        int t = __shfl_up_sync(0xFFFFFFFF, incl, o);
        if (lane >= o) incl += t;
    }
    if (lane == 31) wsum[wid] = incl;
    __syncthreads();
    if (wid == 0) {
        int w = wsum[lane];
#pragma unroll
        for (int o = 1; o < 32; o <<= 1) {
            int t = __shfl_up_sync(0xFFFFFFFF, w, o);
            if (lane >= o) w += t;
        }
        wsum[lane] = w;
    }
    __syncthreads();
    int add = (wid > 0) ? wsum[wid - 1] : 0;
    incl += add;

    if (gid < NNODES) {
        offsets[gid] = incl - v;     // exclusive scan value
        counts[gid]  = 0;            // restore invariant
        cursor[gid]  = 0;            // reset fill cursor
    }
    if (tid == SCAN_TPB - 1) blocksums[blockIdx.x] = incl;
}

// fused scan2+scan3: each block reduces blocksums[0..blk) itself, adds to offsets
__global__ void scan23_kernel(int* __restrict__ offsets, const int* __restrict__ blocksums,
                              int n_edges) {
    __shared__ int red[SCAN_TPB / 32];
    int tid = threadIdx.x;
    int blk = blockIdx.x;

    int part = (tid < blk) ? blocksums[tid] : 0;     // blk <= 292 < 1024
#pragma unroll
    for (int o = 16; o > 0; o >>= 1)
        part += __shfl_down_sync(0xFFFFFFFF, part, o);
    if ((tid & 31) == 0) red[tid >> 5] = part;
    __syncthreads();
    if (tid < 32) {
        int w = (tid < SCAN_TPB / 32) ? red[tid] : 0;
#pragma unroll
        for (int o = 16; o > 0; o >>= 1)
            w += __shfl_down_sync(0xFFFFFFFF, w, o);
        if (tid == 0) red[0] = w;
    }
    __syncthreads();
    int base = red[0];

    int gid = blk * SCAN_TPB + tid;
    if (gid < NNODES) offsets[gid] += base;
    if (gid == 0) offsets[NNODES] = n_edges;
}

__global__ void fill_kernel(const int* __restrict__ rows, const int* __restrict__ cols,
                            const float* __restrict__ vals,
                            const int* __restrict__ offsets, int* __restrict__ cursor,
                            int2* __restrict__ csr_cv, int n) {
    int e = blockIdx.x * blockDim.x + threadIdx.x;
    if (e >= n) return;
    int r = rows[e];
    int pos = offsets[r] + atomicAdd(&cursor[r], 1);
    csr_cv[pos] = make_int2(cols[e], __float_as_int(vals[e]));
}

// ---------------------------------------------------------------------------
__device__ __forceinline__ uint4 pack8(const float f[8]) {
    __half2 h0 = __float22half2_rn(make_float2(f[0], f[1]));
    __half2 h1 = __float22half2_rn(make_float2(f[2], f[3]));
    __half2 h2 = __float22half2_rn(make_float2(f[4], f[5]));
    __half2 h3 = __float22half2_rn(make_float2(f[6], f[7]));
    uint4 o;
    o.x = *reinterpret_cast<unsigned*>(&h0);
    o.y = *reinterpret_cast<unsigned*>(&h1);
    o.z = *reinterpret_cast<unsigned*>(&h2);
    o.w = *reinterpret_cast<unsigned*>(&h3);
    return o;
}
__device__ __forceinline__ void hacc4(__half2 acc[4], uint4 raw, float v) {
    __half2 vh = __half2half2(__float2half_rn(v));
    __half2* h = reinterpret_cast<__half2*>(&raw);
#pragma unroll
    for (int j = 0; j < 4; ++j) acc[j] = __hfma2(vh, h[j], acc[j]);
}
__device__ __forceinline__ void facc8(float a[8], const float4& x0, const float4& x1, float v) {
    a[0] += v*x0.x; a[1] += v*x0.y; a[2] += v*x0.z; a[3] += v*x0.w;
    a[4] += v*x1.x; a[5] += v*x1.y; a[6] += v*x1.z; a[7] += v*x1.w;
}
__device__ __forceinline__ const float4* egoptr(int c, const float4* user,
                                                const float4* item, int l) {
    return (c < USER_NUM) ? (user + (size_t)c * 16 + l * 2)
                          : (item + (size_t)(c - USER_NUM) * 16 + l * 2);
}

// ---------------------------------------------------------------------------
// CSR SpMM, 8 lanes/row, predicated 4-edge batches (clamped idx, zeroed OOB
// weight) — every row takes the parallel path. [R10 proven configuration]
//   MODE 0: fp32 ego gather, fp32 acc -> fp16 store
//   MODE 1: fp16 gather, HFMA2 acc   -> fp16 store
//   MODE 2: like 1, epilogue out = (ego + B + A + s) * 0.25 (fp32)
// ---------------------------------------------------------------------------
template <int MODE>
__global__ __launch_bounds__(256) void spmm_csr_kernel(
        const int*  __restrict__ offsets,
        const int2* __restrict__ cv,
        const uint4* __restrict__ xh,
        const float4* __restrict__ user,
        const float4* __restrict__ item,
        uint4* __restrict__ nexth,
        const uint4* __restrict__ bh,
        const uint4* __restrict__ ah,
        float4* __restrict__ out) {
    int t = blockIdx.x * blockDim.x + threadIdx.x;
    int r = t >> 3;
    int l = t & 7;
    if (r >= NNODES) return;

    int s = __ldg(offsets + r);
    int e = __ldg(offsets + r + 1);

    if (MODE == 0) {
        float a[8];
#pragma unroll
        for (int j = 0; j < 8; ++j) a[j] = 0.f;
        for (int base = s; base < e; base += 4) {
            int last = e - 1;
            int i1 = base + 1 <= last ? base + 1 : last;
            int i2 = base + 2 <= last ? base + 2 : last;
            int i3 = base + 3 <= last ? base + 3 : last;
            int2 c0 = __ldg(cv + base);
            int2 c1 = __ldg(cv + i1);
            int2 c2 = __ldg(cv + i2);
            int2 c3 = __ldg(cv + i3);
            const float4* p0 = egoptr(c0.x, user, item, l);
            const float4* p1 = egoptr(c1.x, user, item, l);
            const float4* p2 = egoptr(c2.x, user, item, l);
            const float4* p3 = egoptr(c3.x, user, item, l);
            float4 x00 = __ldg(p0), x01 = __ldg(p0 + 1);
            float4 x10 = __ldg(p1), x11 = __ldg(p1 + 1);
            float4 x20 = __ldg(p2), x21 = __ldg(p2 + 1);
            float4 x30 = __ldg(p3), x31 = __ldg(p3 + 1);
            float v0 = __int_as_float(c0.y);
            float v1 = (base + 1 < e) ? __int_as_float(c1.y) : 0.f;
            float v2 = (base + 2 < e) ? __int_as_float(c2.y) : 0.f;
            float v3 = (base + 3 < e) ? __int_as_float(c3.y) : 0.f;
            facc8(a, x00, x01, v0);
            facc8(a, x10, x11, v1);
            facc8(a, x20, x21, v2);
            facc8(a, x30, x31, v3);
        }
        nexth[(size_t)r * 8 + l] = pack8(a);
        return;
    }

    // MODE 1 / 2: batch 4
    __half2 acc[4];
    __half2 z = __half2half2(__float2half_rn(0.f));
#pragma unroll
    for (int j = 0; j < 4; ++j) acc[j] = z;

    for (int base = s; base < e; base += 4) {
        int last = e - 1;
        int i1 = base + 1 <= last ? base + 1 : last;
        int i2 = base + 2 <= last ? base + 2 : last;
        int i3 = base + 3 <= last ? base + 3 : last;
        int2 c0 = __ldg(cv + base);
        int2 c1 = __ldg(cv + i1);
        int2 c2 = __ldg(cv + i2);
        int2 c3 = __ldg(cv + i3);
        uint4 x0 = __ldg(xh + (size_t)c0.x * 8 + l);
        uint4 x1 = __ldg(xh + (size_t)c1.x * 8 + l);
        uint4 x2 = __ldg(xh + (size_t)c2.x * 8 + l);
        uint4 x3 = __ldg(xh + (size_t)c3.x * 8 + l);
        float v0 = __int_as_float(c0.y);
        float v1 = (base + 1 < e) ? __int_as_float(c1.y) : 0.f;
        float v2 = (base + 2 < e) ? __int_as_float(c2.y) : 0.f;
        float v3 = (base + 3 < e) ? __int_as_float(c3.y) : 0.f;
        hacc4(acc, x0, v0);
        hacc4(acc, x1, v1);
        hacc4(acc, x2, v2);
        hacc4(acc, x3, v3);
    }

    if (MODE == 1) {
        uint4 o;
        o.x = *reinterpret_cast<unsigned*>(&acc[0]);
        o.y = *reinterpret_cast<unsigned*>(&acc[1]);
        o.z = *reinterpret_cast<unsigned*>(&acc[2]);
        o.w = *reinterpret_cast<unsigned*>(&acc[3]);
        nexth[(size_t)r * 8 + l] = o;
    } else {
        size_t fo = (size_t)r * 16 + l * 2;
        const float4* egop = (r < USER_NUM)
            ? (user + fo)
            : (item + (size_t)(r - USER_NUM) * 16 + l * 2);
        float4 e0 = __ldg(egop);
        float4 e1 = __ldg(egop + 1);
        uint4 braw = __ldg(bh + (size_t)r * 8 + l);
        uint4 araw = __ldg(ah + (size_t)r * 8 + l);
        __half2* bhh = reinterpret_cast<__half2*>(&braw);
        __half2* ahh = reinterpret_cast<__half2*>(&araw);
        float2 b0 = __half22float2(bhh[0]), b1 = __half22float2(bhh[1]);
        float2 b2 = __half22float2(bhh[2]), b3 = __half22float2(bhh[3]);
        float2 q0 = __half22float2(ahh[0]), q1 = __half22float2(ahh[1]);
        float2 q2 = __half22float2(ahh[2]), q3 = __half22float2(ahh[3]);
        float2 s0 = __half22float2(acc[0]), s1 = __half22float2(acc[1]);
        float2 s2 = __half22float2(acc[2]), s3 = __half22float2(acc[3]);
        float4 o0, o1;
        o0.x = (e0.x + b0.x + q0.x + s0.x) * 0.25f;
        o0.y = (e0.y + b0.y + q0.y + s0.y) * 0.25f;
        o0.z = (e0.z + b1.x + q1.x + s1.x) * 0.25f;
        o0.w = (e0.w + b1.y + q1.y + s1.y) * 0.25f;
        o1.x = (e1.x + b2.x + q2.x + s2.x) * 0.25f;
        o1.y = (e1.y + b2.y + q2.y + s2.y) * 0.25f;
        o1.z = (e1.z + b3.x + q3.x + s3.x) * 0.25f;
        o1.w = (e1.w + b3.y + q3.y + s3.y) * 0.25f;
        out[fo]     = o0;
        out[fo + 1] = o1;
    }
}

// ---------------------------------------------------------------------------
extern "C" void kernel_launch(void* const* d_in, const int* in_sizes, int n_in,
                              void* d_out, int out_size) {
    const float* user = (const float*)d_in[0];
    const float* item = (const float*)d_in[1];
    const float* vals = (const float*)d_in[2];
    const int*   rows = (const int*)  d_in[3];
    const int*   cols = (const int*)  d_in[4];
    const int n_edges = in_sizes[2];

    float4* out = (float4*)d_out;

    int *counts, *cursor, *offsets, *blocksums;
    int2 *csr_cv;
    uint4 *A, *B;
    cudaGetSymbolAddress((void**)&counts,    g_counts);
    cudaGetSymbolAddress((void**)&cursor,    g_cursor);
    cudaGetSymbolAddress((void**)&offsets,   g_offsets);
    cudaGetSymbolAddress((void**)&blocksums, g_blocksums);
    cudaGetSymbolAddress((void**)&csr_cv,    g_csr_cv);
    cudaGetSymbolAddress((void**)&A,         g_bufA);
    cudaGetSymbolAddress((void**)&B,         g_bufB);

    const int TPB = 256;
    const int grid_edges = (n_edges + TPB - 1) / TPB;
    const int grid_spmm  = (NNODES * 8 + TPB - 1) / TPB;

    // ---- CSR build (4 kernels; counts==0 invariant at entry) ----
    hist_kernel<<<grid_edges, TPB>>>(rows, counts, n_edges);
    scan1_kernel<<<NSCANBLK, SCAN_TPB>>>(counts, cursor, offsets, blocksums);
    scan23_kernel<<<NSCANBLK, SCAN_TPB>>>(offsets, blocksums, n_edges);
    fill_kernel<<<grid_edges, TPB>>>(rows, cols, vals, offsets, cursor,
                                     csr_cv, n_edges);

    // ---- 3 propagation layers ----
    spmm_csr_kernel<0><<<grid_spmm, TPB>>>(offsets, csr_cv, nullptr,
                                           (const float4*)user, (const float4*)item,
                                           B, nullptr, nullptr, nullptr);
    spmm_csr_kernel<1><<<grid_spmm, TPB>>>(offsets, csr_cv, B,
                                           (const float4*)user, (const float4*)item,
                                           A, nullptr, nullptr, nullptr);
    spmm_csr_kernel<2><<<grid_spmm, TPB>>>(offsets, csr_cv, A,
                                           (const float4*)user, (const float4*)item,
                                           nullptr, B, A, out);
}